// round 4
// baseline (speedup 1.0000x reference)
#include <cuda_runtime.h>
#include <math.h>

#define NN    10000
#define E0    160000
#define ET    (E0 + NN)
#define H     8
#define HID   256
#define NC    40
#define EPSV  1e-5f

// ---------------- scratch (static device allocations) ----------------
__device__ float    g_h0[(size_t)NN * HID];          // layer0 features [N, 8*32]
__device__ float    g_hbn0[(size_t)NN * HID];        // post BN+ELU layer0
__device__ float    g_h1[(size_t)NN * H * HID];      // layer1 features [N, 8*256] (82MB)
__device__ float    g_hbn1[(size_t)NN * HID];        // post BN+ELU+resid layer1
__device__ float    g_acc[(size_t)NN * HID];         // aggregation accumulator
__device__ float    g_ssrc[NN * H];
__device__ float    g_sdst[NN * H];
__device__ unsigned g_m[NN * H];                     // segment max (flipped-uint)
__device__ float    g_den[NN * H];                   // softmax denominators
__device__ float    g_esc[(size_t)ET * H];           // per-edge scores -> exp -> alpha
__device__ float    g_bnsum[HID];
__device__ float    g_bnsq[HID];

// ---------------- helpers ----------------
__device__ __forceinline__ unsigned fflip(float f) {
    unsigned u = __float_as_uint(f);
    return u ^ ((u & 0x80000000u) ? 0xFFFFFFFFu : 0x80000000u);
}
__device__ __forceinline__ float funflip(unsigned u) {
    return __uint_as_float(u ^ ((u & 0x80000000u) ? 0x80000000u : 0xFFFFFFFFu));
}
__device__ __forceinline__ void edge_sd(const int* __restrict__ ei, int e, int& s, int& d) {
    if (e < E0) { s = ei[e]; d = ei[E0 + e]; }
    else        { s = e - E0; d = s; }          // self-loops
}

// ---------------- generic fp32 tiled GEMM:  C[M,N] = A[M,K] @ B[K,N] (+bias) ----------------
// 64x64 tile, BK=16, 256 threads, 4x4 per thread.
__global__ void gemm_kernel(const float* __restrict__ A, const float* __restrict__ B,
                            const float* __restrict__ bias, float* __restrict__ C,
                            int M, int N, int K) {
    __shared__ float As[16][64];
    __shared__ float Bs[16][64];
    const int tid = threadIdx.x;
    const int tx = tid & 15, ty = tid >> 4;
    const int row0 = blockIdx.y * 64;
    const int col0 = blockIdx.x * 64;

    float acc[4][4] = {};
    for (int k0 = 0; k0 < K; k0 += 16) {
        #pragma unroll
        for (int i = 0; i < 4; i++) {
            int m  = (tid >> 4) + i * 16;     // 0..63
            int kk = tid & 15;
            int gm = row0 + m;
            float v = 0.f;
            if (gm < M) v = A[(size_t)gm * K + k0 + kk];
            As[kk][m] = v;
        }
        #pragma unroll
        for (int i = 0; i < 4; i++) {
            int kk = (tid >> 6) + i * 4;      // 0..15
            int nn = tid & 63;
            int gn = col0 + nn;
            float v = 0.f;
            if (gn < N) v = B[(size_t)(k0 + kk) * N + gn];
            Bs[kk][nn] = v;
        }
        __syncthreads();
        #pragma unroll
        for (int kk = 0; kk < 16; kk++) {
            float ra[4], rb[4];
            #pragma unroll
            for (int i = 0; i < 4; i++) ra[i] = As[kk][ty * 4 + i];
            #pragma unroll
            for (int j = 0; j < 4; j++) rb[j] = Bs[kk][tx * 4 + j];
            #pragma unroll
            for (int i = 0; i < 4; i++)
                #pragma unroll
                for (int j = 0; j < 4; j++)
                    acc[i][j] += ra[i] * rb[j];
        }
        __syncthreads();
    }
    #pragma unroll
    for (int i = 0; i < 4; i++) {
        int gm = row0 + ty * 4 + i;
        if (gm >= M) continue;
        #pragma unroll
        for (int j = 0; j < 4; j++) {
            int gn = col0 + tx * 4 + j;
            if (gn < N) C[(size_t)gm * N + gn] = acc[i][j] + (bias ? bias[gn] : 0.f);
        }
    }
}

// ---------------- attention scores per (node, head) ----------------
__global__ void scores_kernel(const float* __restrict__ h, const float* __restrict__ asr,
                              const float* __restrict__ ads, int C) {
    int gw   = (blockIdx.x * blockDim.x + threadIdx.x) >> 5;
    int lane = threadIdx.x & 31;
    if (gw >= NN * H) return;
    int n = gw / H, hh = gw % H;
    const float* hp = h + (size_t)n * H * C + (size_t)hh * C;
    const float* a1 = asr + hh * C;
    const float* a2 = ads + hh * C;
    float s1 = 0.f, s2 = 0.f;
    for (int c = lane; c < C; c += 32) {
        float v = hp[c];
        s1 += v * a1[c];
        s2 += v * a2[c];
    }
    #pragma unroll
    for (int o = 16; o; o >>= 1) {
        s1 += __shfl_down_sync(0xffffffffu, s1, o);
        s2 += __shfl_down_sync(0xffffffffu, s2, o);
    }
    if (lane == 0) { g_ssrc[gw] = s1; g_sdst[gw] = s2; }
}

// ---------------- per-layer zero/init kernels ----------------
__global__ void zero_seg_kernel() {
    int i = blockIdx.x * blockDim.x + threadIdx.x;
    if (i < NN * H) { g_m[i] = 0u; g_den[i] = 0.f; }   // 0u unflips below every float
}
__global__ void zero_acc_kernel() {
    size_t i = (size_t)blockIdx.x * blockDim.x + threadIdx.x;
    if (i < (size_t)NN * HID) g_acc[i] = 0.f;
}
__global__ void zero_bn_kernel() {
    int i = threadIdx.x;
    g_bnsum[i] = 0.f; g_bnsq[i] = 0.f;
}

// ---------------- edge softmax passes ----------------
__global__ void edge_p1_kernel(const int* __restrict__ ei) {
    int idx = blockIdx.x * blockDim.x + threadIdx.x;
    if (idx >= ET * H) return;
    int e = idx >> 3, hh = idx & 7;
    int s, d; edge_sd(ei, e, s, d);
    float sc = g_ssrc[s * H + hh] + g_sdst[d * H + hh];
    sc = sc > 0.f ? sc : 0.2f * sc;              // leaky_relu(0.2)
    g_esc[idx] = sc;
    atomicMax(&g_m[d * H + hh], fflip(sc));
}
__global__ void edge_p2_kernel(const int* __restrict__ ei) {
    int idx = blockIdx.x * blockDim.x + threadIdx.x;
    if (idx >= ET * H) return;
    int e = idx >> 3, hh = idx & 7;
    int s, d; edge_sd(ei, e, s, d);
    float m  = funflip(g_m[d * H + hh]);
    float ev = expf(g_esc[idx] - m);
    g_esc[idx] = ev;
    atomicAdd(&g_den[d * H + hh], ev);
}
__global__ void edge_alpha_kernel(const int* __restrict__ ei) {
    int idx = blockIdx.x * blockDim.x + threadIdx.x;
    if (idx >= ET * H) return;
    int e = idx >> 3, hh = idx & 7;
    int s, d; edge_sd(ei, e, s, d);
    g_esc[idx] = g_esc[idx] / g_den[d * H + hh];
}

// ---------------- aggregation ----------------
// layer 0: C=32 per head, concat -> out col == feature col
__global__ void agg0_kernel(const int* __restrict__ ei, const float* __restrict__ h0) {
    int e = blockIdx.x;          // one edge per block
    int col = threadIdx.x;       // 0..255
    int s, d; edge_sd(ei, e, s, d);
    int hh = col >> 5;
    float alpha = g_esc[e * H + hh];
    atomicAdd(&g_acc[(size_t)d * HID + col], alpha * h0[(size_t)s * HID + col]);
}
// layer 1: C=256 per head, head-sum folded in registers (mean applied later)
__global__ void agg1_kernel(const int* __restrict__ ei, const float* __restrict__ h1) {
    int e = blockIdx.x;
    int col = threadIdx.x;       // 0..255
    int s, d; edge_sd(ei, e, s, d);
    __shared__ float al[H];
    if (col < H) al[col] = g_esc[e * H + col];
    __syncthreads();
    const float* hp = h1 + (size_t)s * (H * HID) + col;
    float sum = 0.f;
    #pragma unroll
    for (int hh = 0; hh < H; hh++) sum += al[hh] * hp[(size_t)hh * HID];
    atomicAdd(&g_acc[(size_t)d * HID + col], sum);
}

// ---------------- batch norm ----------------
__global__ void bn_stats_kernel(const float* __restrict__ bias, float scale) {
    int c = threadIdx.x;               // 256 threads = 256 cols
    float b = bias[c];
    int r0 = blockIdx.x * 50;
    int r1 = r0 + 50; if (r1 > NN) r1 = NN;
    float s = 0.f, q = 0.f;
    for (int r = r0; r < r1; r++) {
        float v = g_acc[(size_t)r * HID + c] * scale + b;
        s += v; q += v * v;
    }
    atomicAdd(&g_bnsum[c], s);
    atomicAdd(&g_bnsq[c], q);
}
__global__ void bn_apply_kernel(const float* __restrict__ bias, float scale,
                                const float* __restrict__ gma, const float* __restrict__ bet,
                                const float* __restrict__ resid, float* __restrict__ out) {
    size_t i = (size_t)blockIdx.x * blockDim.x + threadIdx.x;
    if (i >= (size_t)NN * HID) return;
    int c = (int)(i & 255);
    float v   = g_acc[i] * scale + bias[c];
    float mu  = g_bnsum[c] * (1.0f / NN);
    float var = g_bnsq[c]  * (1.0f / NN) - mu * mu;
    float y = gma[c] * (v - mu) * rsqrtf(var + EPSV) + bet[c];
    y = y > 0.f ? y : expm1f(y);                  // ELU
    if (resid) y += resid[i];
    out[i] = y;
}

// ---------------- launch ----------------
extern "C" void kernel_launch(void* const* d_in, const int* in_sizes, int n_in,
                              void* d_out, int out_size) {
    const float* x   = (const float*)d_in[0];
    const int*   ei  = (const int*)  d_in[1];
    const float* W0  = (const float*)d_in[2];
    const float* as0 = (const float*)d_in[3];
    const float* ad0 = (const float*)d_in[4];
    const float* b0  = (const float*)d_in[5];
    const float* gm0 = (const float*)d_in[6];
    const float* be0 = (const float*)d_in[7];
    const float* W1  = (const float*)d_in[8];
    const float* as1 = (const float*)d_in[9];
    const float* ad1 = (const float*)d_in[10];
    const float* b1  = (const float*)d_in[11];
    const float* gm1 = (const float*)d_in[12];
    const float* be1 = (const float*)d_in[13];
    const float* Wc  = (const float*)d_in[14];
    const float* bc  = (const float*)d_in[15];
    float* out = (float*)d_out;

    float *h0, *hbn0, *h1, *hbn1;
    cudaGetSymbolAddress((void**)&h0,   g_h0);
    cudaGetSymbolAddress((void**)&hbn0, g_hbn0);
    cudaGetSymbolAddress((void**)&h1,   g_h1);
    cudaGetSymbolAddress((void**)&hbn1, g_hbn1);

    const int TB = 256;
    const int nEH   = ET * H;
    const int gEH   = (nEH + TB - 1) / TB;
    const int gNH32 = (NN * H * 32 + TB - 1) / TB;   // scores: 1 warp per (n,h)
    const int gNF   = (NN * HID + TB - 1) / TB;

    // ===== layer 0 =====
    {
        dim3 g((HID + 63) / 64, (NN + 63) / 64);
        gemm_kernel<<<g, TB>>>(x, W0, nullptr, h0, NN, HID, 256);
    }
    scores_kernel<<<gNH32, TB>>>(h0, as0, ad0, 32);
    zero_seg_kernel<<<(NN * H + TB - 1) / TB, TB>>>();
    zero_acc_kernel<<<gNF, TB>>>();
    edge_p1_kernel<<<gEH, TB>>>(ei);
    edge_p2_kernel<<<gEH, TB>>>(ei);
    edge_alpha_kernel<<<gEH, TB>>>(ei);
    agg0_kernel<<<ET, TB>>>(ei, h0);
    zero_bn_kernel<<<1, HID>>>();
    bn_stats_kernel<<<(NN + 49) / 50, HID>>>(b0, 1.0f);
    bn_apply_kernel<<<gNF, TB>>>(b0, 1.0f, gm0, be0, nullptr, hbn0);

    // ===== layer 1 =====
    {
        dim3 g((H * HID + 63) / 64, (NN + 63) / 64);
        gemm_kernel<<<g, TB>>>(hbn0, W1, nullptr, h1, NN, H * HID, 256);
    }
    scores_kernel<<<gNH32, TB>>>(h1, as1, ad1, 256);
    zero_seg_kernel<<<(NN * H + TB - 1) / TB, TB>>>();
    zero_acc_kernel<<<gNF, TB>>>();
    edge_p1_kernel<<<gEH, TB>>>(ei);
    edge_p2_kernel<<<gEH, TB>>>(ei);
    edge_alpha_kernel<<<gEH, TB>>>(ei);
    agg1_kernel<<<ET, TB>>>(ei, h1);
    zero_bn_kernel<<<1, HID>>>();
    bn_stats_kernel<<<(NN + 49) / 50, HID>>>(b1, 0.125f);            // mean over 8 heads
    bn_apply_kernel<<<gNF, TB>>>(b1, 0.125f, gm1, be1, hbn0, hbn1);  // + residual

    // ===== classifier =====
    {
        dim3 g((NC + 63) / 64, (NN + 63) / 64);
        gemm_kernel<<<g, TB>>>(hbn1, Wc, bc, out, NN, NC, 256);
    }
}

// round 9
// speedup vs baseline: 1.2398x; 1.2398x over previous
#include <cuda_runtime.h>
#include <cuda_bf16.h>
#include <math.h>
#include <stdint.h>

#define NN    10000
#define E0    160000
#define ET    (E0 + NN)
#define H     8
#define HID   256
#define NC    40
#define EPSV  1e-5f
#define KSP   768          // split-K: [hi | lo | hi] x [hi | hi | lo]

// ---------------- scratch (static device allocations) ----------------
__device__ float    g_h0[(size_t)NN * HID];
__device__ float    g_hbn0[(size_t)NN * HID];
__device__ float    g_h1[(size_t)NN * H * HID];      // 82MB
__device__ float    g_hbn1[(size_t)NN * HID];
__device__ float    g_acc[(size_t)NN * HID];
__device__ float    g_ssrc[NN * H];
__device__ float    g_sdst[NN * H];
__device__ unsigned g_m[NN * H];
__device__ float    g_den[NN * H];
__device__ float    g_esc[(size_t)ET * H];
__device__ float    g_bnsum[HID];
__device__ float    g_bnsq[HID];

// split bf16 operands (K = 768)
__device__ __nv_bfloat16 g_xsp [(size_t)NN * KSP];    // x split [N, 768]
__device__ __nv_bfloat16 g_a1sp[(size_t)NN * KSP];    // hbn0 split
__device__ __nv_bfloat16 g_w0sp[(size_t)256 * KSP];   // W0^T split [No, 768]
__device__ __nv_bfloat16 g_w1sp[(size_t)2048 * KSP];  // W1^T split

// ---------------- helpers ----------------
__device__ __forceinline__ uint32_t smem_u32(const void* p) {
    uint32_t a;
    asm("{ .reg .u64 t; cvta.to.shared.u64 t, %1; cvt.u32.u64 %0, t; }" : "=r"(a) : "l"(p));
    return a;
}
__device__ __forceinline__ void cp16(uint32_t dst, const void* src, bool pred) {
    int sz = pred ? 16 : 0;
    asm volatile("cp.async.cg.shared.global [%0], [%1], 16, %2;"
                 :: "r"(dst), "l"(src), "r"(sz));
}
__device__ __forceinline__ void ldm_x4(uint32_t* r, uint32_t addr) {
    asm volatile("ldmatrix.sync.aligned.m8n8.x4.shared.b16 {%0,%1,%2,%3}, [%4];"
                 : "=r"(r[0]), "=r"(r[1]), "=r"(r[2]), "=r"(r[3]) : "r"(addr));
}
__device__ __forceinline__ void mma16816(float* c, const uint32_t* a, uint32_t b0, uint32_t b1) {
    asm volatile("mma.sync.aligned.m16n8k16.row.col.f32.bf16.bf16.f32 "
                 "{%0,%1,%2,%3}, {%4,%5,%6,%7}, {%8,%9}, {%0,%1,%2,%3};"
                 : "+f"(c[0]), "+f"(c[1]), "+f"(c[2]), "+f"(c[3])
                 : "r"(a[0]), "r"(a[1]), "r"(a[2]), "r"(a[3]), "r"(b0), "r"(b1));
}
__device__ __forceinline__ unsigned fflip(float f) {
    unsigned u = __float_as_uint(f);
    return u ^ ((u & 0x80000000u) ? 0xFFFFFFFFu : 0x80000000u);
}
__device__ __forceinline__ float funflip(unsigned u) {
    return __uint_as_float(u ^ ((u & 0x80000000u) ? 0x80000000u : 0xFFFFFFFFu));
}
__device__ __forceinline__ void edge_sd(const int* __restrict__ ei, int e, int& s, int& d) {
    if (e < E0) { s = ei[e]; d = ei[E0 + e]; }
    else        { s = e - E0; d = s; }
}

// ---------------- split conversion kernels ----------------
// A side: [n][256] fp32 -> [n][768] bf16 as [hi | lo | hi]
__global__ void split_a_kernel(const float* __restrict__ src, __nv_bfloat16* __restrict__ dst,
                               int rows) {
    int i = blockIdx.x * blockDim.x + threadIdx.x;
    if (i >= rows * 256) return;
    int r = i >> 8, k = i & 255;
    float v = src[i];
    __nv_bfloat16 h = __float2bfloat16(v);
    __nv_bfloat16 l = __float2bfloat16(v - __bfloat162float(h));
    __nv_bfloat16* p = dst + (size_t)r * KSP;
    p[k] = h; p[256 + k] = l; p[512 + k] = h;
}
// B side: W [256][No] fp32 -> Wt [No][768] bf16 as [hi | hi | lo]
__global__ void split_bT_kernel(const float* __restrict__ W, __nv_bfloat16* __restrict__ dst,
                                int No) {
    int i = blockIdx.x * blockDim.x + threadIdx.x;
    if (i >= 256 * No) return;
    int k = i / No, n = i % No;
    float v = W[i];
    __nv_bfloat16 h = __float2bfloat16(v);
    __nv_bfloat16 l = __float2bfloat16(v - __bfloat162float(h));
    __nv_bfloat16* p = dst + (size_t)n * KSP;
    p[k] = h; p[256 + k] = h; p[512 + k] = l;
}

// ---------------- bf16 mma.sync GEMM: C[M,Nt] = A[M,768] @ Bt[Nt,768]^T ----------------
// tile 128x128, BK=32, 8 warps (4 M x 2 N), warp tile 32x64, cp.async double buffer.
#define BK   32
#define KT   (KSP / BK)        // 24
#define SROW 40                // padded row stride (bf16 elems) -> 80 bytes
__global__ __launch_bounds__(256, 1)
void mma_gemm_kernel(const __nv_bfloat16* __restrict__ A, const __nv_bfloat16* __restrict__ Bt,
                     float* __restrict__ C, int M, int Nt) {
    __shared__ __align__(16) __nv_bfloat16 sA[2][128 * SROW];
    __shared__ __align__(16) __nv_bfloat16 sB[2][128 * SROW];

    const int tid  = threadIdx.x;
    const int lane = tid & 31, wid = tid >> 5;
    const int wm = (wid & 3) * 32;        // warp M offset in tile
    const int wn = (wid >> 2) * 64;       // warp N offset in tile
    const int m0 = blockIdx.y * 128;
    const int n0 = blockIdx.x * 128;

    const uint32_t sa0 = smem_u32(sA[0]), sa1 = smem_u32(sA[1]);
    const uint32_t sb0 = smem_u32(sB[0]), sb1 = smem_u32(sB[1]);

    // per-thread load slots: 2 A-chunks + 2 B-chunks of 16B per tile
    int v0 = tid, v1 = tid + 256;
    int ar0 = v0 >> 2, ac0 = v0 & 3;
    int ar1 = v1 >> 2, ac1 = v1 & 3;
    int gm0r = m0 + ar0, gm1r = m0 + ar1;
    bool p0 = gm0r < M, p1 = gm1r < M;
    int cm0 = p0 ? gm0r : 0, cm1 = p1 ? gm1r : 0;

    float c[2][8][4];
    #pragma unroll
    for (int i = 0; i < 2; i++)
        #pragma unroll
        for (int j = 0; j < 8; j++)
            #pragma unroll
            for (int q = 0; q < 4; q++) c[i][j][q] = 0.f;

    auto issue = [&](int kt) {
        int buf = kt & 1;
        uint32_t da = buf ? sa1 : sa0;
        uint32_t db = buf ? sb1 : sb0;
        int k0 = kt * BK;
        cp16(da + (uint32_t)(ar0 * 80 + ac0 * 16), A + (size_t)cm0 * KSP + k0 + ac0 * 8, p0);
        cp16(da + (uint32_t)(ar1 * 80 + ac1 * 16), A + (size_t)cm1 * KSP + k0 + ac1 * 8, p1);
        cp16(db + (uint32_t)(ar0 * 80 + ac0 * 16), Bt + (size_t)(n0 + ar0) * KSP + k0 + ac0 * 8, true);
        cp16(db + (uint32_t)(ar1 * 80 + ac1 * 16), Bt + (size_t)(n0 + ar1) * KSP + k0 + ac1 * 8, true);
        asm volatile("cp.async.commit_group;");
    };

    issue(0);
    for (int kt = 0; kt < KT; kt++) {
        if (kt + 1 < KT) {
            issue(kt + 1);
            asm volatile("cp.async.wait_group 1;");
        } else {
            asm volatile("cp.async.wait_group 0;");
        }
        __syncthreads();

        uint32_t da = (kt & 1) ? sa1 : sa0;
        uint32_t db = (kt & 1) ? sb1 : sb0;
        #pragma unroll
        for (int ks = 0; ks < 2; ks++) {
            uint32_t a[2][4], b[4][4];
            #pragma unroll
            for (int mi = 0; mi < 2; mi++) {
                uint32_t addr = da + (uint32_t)((wm + mi * 16 + (lane & 15)) * 80
                                              + (ks * 16 + (lane >> 4) * 8) * 2);
                ldm_x4(a[mi], addr);
            }
            #pragma unroll
            for (int ni = 0; ni < 4; ni++) {
                uint32_t addr = db + (uint32_t)((wn + ni * 16 + ((lane >> 4) << 3) + (lane & 7)) * 80
                                              + (ks * 16 + ((lane >> 3) & 1) * 8) * 2);
                ldm_x4(b[ni], addr);
            }
            #pragma unroll
            for (int mi = 0; mi < 2; mi++)
                #pragma unroll
                for (int nj = 0; nj < 8; nj++)
                    mma16816(c[mi][nj], a[mi], b[nj >> 1][(nj & 1) * 2 + 0],
                             b[nj >> 1][(nj & 1) * 2 + 1]);
        }
        __syncthreads();
    }

    // epilogue
    #pragma unroll
    for (int mi = 0; mi < 2; mi++) {
        int gm = m0 + wm + mi * 16 + (lane >> 2);
        #pragma unroll
        for (int nj = 0; nj < 8; nj++) {
            int gn = n0 + wn + nj * 8 + (lane & 3) * 2;
            if (gm < M)
                *reinterpret_cast<float2*>(C + (size_t)gm * Nt + gn) =
                    make_float2(c[mi][nj][0], c[mi][nj][1]);
            if (gm + 8 < M)
                *reinterpret_cast<float2*>(C + (size_t)(gm + 8) * Nt + gn) =
                    make_float2(c[mi][nj][2], c[mi][nj][3]);
        }
    }
}

// ---------------- SIMT GEMM (classifier only) ----------------
__global__ void gemm_kernel(const float* __restrict__ A, const float* __restrict__ B,
                            const float* __restrict__ bias, float* __restrict__ C,
                            int M, int N, int K) {
    __shared__ float As[16][64];
    __shared__ float Bs[16][64];
    const int tid = threadIdx.x;
    const int tx = tid & 15, ty = tid >> 4;
    const int row0 = blockIdx.y * 64;
    const int col0 = blockIdx.x * 64;
    float acc[4][4] = {};
    for (int k0 = 0; k0 < K; k0 += 16) {
        #pragma unroll
        for (int i = 0; i < 4; i++) {
            int m = (tid >> 4) + i * 16, kk = tid & 15, gm = row0 + m;
            As[kk][m] = (gm < M) ? A[(size_t)gm * K + k0 + kk] : 0.f;
        }
        #pragma unroll
        for (int i = 0; i < 4; i++) {
            int kk = (tid >> 6) + i * 4, nn = tid & 63, gn = col0 + nn;
            Bs[kk][nn] = (gn < N) ? B[(size_t)(k0 + kk) * N + gn] : 0.f;
        }
        __syncthreads();
        #pragma unroll
        for (int kk = 0; kk < 16; kk++) {
            float ra[4], rb[4];
            #pragma unroll
            for (int i = 0; i < 4; i++) ra[i] = As[kk][ty * 4 + i];
            #pragma unroll
            for (int j = 0; j < 4; j++) rb[j] = Bs[kk][tx * 4 + j];
            #pragma unroll
            for (int i = 0; i < 4; i++)
                #pragma unroll
                for (int j = 0; j < 4; j++)
                    acc[i][j] += ra[i] * rb[j];
        }
        __syncthreads();
    }
    #pragma unroll
    for (int i = 0; i < 4; i++) {
        int gm = row0 + ty * 4 + i;
        if (gm >= M) continue;
        #pragma unroll
        for (int j = 0; j < 4; j++) {
            int gn = col0 + tx * 4 + j;
            if (gn < N) C[(size_t)gm * N + gn] = acc[i][j] + (bias ? bias[gn] : 0.f);
        }
    }
}

// ---------------- attention scores per (node, head) ----------------
__global__ void scores_kernel(const float* __restrict__ h, const float* __restrict__ asr,
                              const float* __restrict__ ads, int C) {
    int gw = (blockIdx.x * blockDim.x + threadIdx.x) >> 5;
    int lane = threadIdx.x & 31;
    if (gw >= NN * H) return;
    int n = gw / H, hh = gw % H;
    const float* hp = h + (size_t)n * H * C + (size_t)hh * C;
    const float* a1 = asr + hh * C;
    const float* a2 = ads + hh * C;
    float s1 = 0.f, s2 = 0.f;
    for (int c = lane; c < C; c += 32) {
        float v = hp[c];
        s1 += v * a1[c];
        s2 += v * a2[c];
    }
    #pragma unroll
    for (int o = 16; o; o >>= 1) {
        s1 += __shfl_down_sync(0xffffffffu, s1, o);
        s2 += __shfl_down_sync(0xffffffffu, s2, o);
    }
    if (lane == 0) { g_ssrc[gw] = s1; g_sdst[gw] = s2; }
}

// ---------------- zero/init ----------------
__global__ void zero_seg_kernel() {
    int i = blockIdx.x * blockDim.x + threadIdx.x;
    if (i < NN * H) { g_m[i] = 0u; g_den[i] = 0.f; }
}
__global__ void zero_acc_kernel() {
    size_t i = (size_t)blockIdx.x * blockDim.x + threadIdx.x;
    if (i < (size_t)NN * HID) g_acc[i] = 0.f;
}
__global__ void zero_bn_kernel() {
    int i = threadIdx.x;
    g_bnsum[i] = 0.f; g_bnsq[i] = 0.f;
}

// ---------------- edge softmax passes ----------------
__global__ void edge_p1_kernel(const int* __restrict__ ei) {
    int idx = blockIdx.x * blockDim.x + threadIdx.x;
    if (idx >= ET * H) return;
    int e = idx >> 3, hh = idx & 7;
    int s, d; edge_sd(ei, e, s, d);
    float sc = g_ssrc[s * H + hh] + g_sdst[d * H + hh];
    sc = sc > 0.f ? sc : 0.2f * sc;
    g_esc[idx] = sc;
    atomicMax(&g_m[d * H + hh], fflip(sc));
}
__global__ void edge_p2_kernel(const int* __restrict__ ei) {
    int idx = blockIdx.x * blockDim.x + threadIdx.x;
    if (idx >= ET * H) return;
    int e = idx >> 3, hh = idx & 7;
    int s, d; edge_sd(ei, e, s, d);
    float m = funflip(g_m[d * H + hh]);
    float ev = expf(g_esc[idx] - m);
    g_esc[idx] = ev;
    atomicAdd(&g_den[d * H + hh], ev);
}

// ---------------- aggregation (alpha normalization fused) ----------------
__global__ void agg0_kernel(const int* __restrict__ ei, const float* __restrict__ h0) {
    int e = blockIdx.x;
    int col = threadIdx.x;
    int s, d; edge_sd(ei, e, s, d);
    __shared__ float al[H];
    if (col < H) al[col] = g_esc[e * H + col] / g_den[d * H + col];
    __syncthreads();
    atomicAdd(&g_acc[(size_t)d * HID + col], al[col >> 5] * h0[(size_t)s * HID + col]);
}
__global__ void agg1_kernel(const int* __restrict__ ei, const float* __restrict__ h1) {
    int e = blockIdx.x;
    int col = threadIdx.x;
    int s, d; edge_sd(ei, e, s, d);
    __shared__ float al[H];
    if (col < H) al[col] = g_esc[e * H + col] / g_den[d * H + col];
    __syncthreads();
    const float* hp = h1 + (size_t)s * (H * HID) + col;
    float sum = 0.f;
    #pragma unroll
    for (int hh = 0; hh < H; hh++) sum += al[hh] * hp[(size_t)hh * HID];
    atomicAdd(&g_acc[(size_t)d * HID + col], sum);
}

// ---------------- batch norm ----------------
__global__ void bn_stats_kernel(const float* __restrict__ bias, float scale) {
    int c = threadIdx.x;
    float b = bias[c];
    int r0 = blockIdx.x * 50;
    int r1 = r0 + 50; if (r1 > NN) r1 = NN;
    float s = 0.f, q = 0.f;
    for (int r = r0; r < r1; r++) {
        float v = g_acc[(size_t)r * HID + c] * scale + b;
        s += v; q += v * v;
    }
    atomicAdd(&g_bnsum[c], s);
    atomicAdd(&g_bnsq[c], q);
}
__global__ void bn_apply_kernel(const float* __restrict__ bias, float scale,
                                const float* __restrict__ gma, const float* __restrict__ bet,
                                const float* __restrict__ resid, float* __restrict__ out,
                                __nv_bfloat16* __restrict__ asp) {
    size_t i = (size_t)blockIdx.x * blockDim.x + threadIdx.x;
    if (i >= (size_t)NN * HID) return;
    int c = (int)(i & 255);
    float v = g_acc[i] * scale + bias[c];
    float mu = g_bnsum[c] * (1.0f / NN);
    float var = g_bnsq[c] * (1.0f / NN) - mu * mu;
    float y = gma[c] * (v - mu) * rsqrtf(var + EPSV) + bet[c];
    y = y > 0.f ? y : expm1f(y);
    if (resid) y += resid[i];
    out[i] = y;
    if (asp) {    // fused [hi | lo | hi] split for the next GEMM's A operand
        size_t r = i >> 8;
        __nv_bfloat16 h = __float2bfloat16(y);
        __nv_bfloat16 l = __float2bfloat16(y - __bfloat162float(h));
        __nv_bfloat16* p = asp + r * KSP;
        p[c] = h; p[256 + c] = l; p[512 + c] = h;
    }
}

// ---------------- launch ----------------
extern "C" void kernel_launch(void* const* d_in, const int* in_sizes, int n_in,
                              void* d_out, int out_size) {
    const float* x   = (const float*)d_in[0];
    const int*   ei  = (const int*)  d_in[1];
    const float* W0  = (const float*)d_in[2];
    const float* as0 = (const float*)d_in[3];
    const float* ad0 = (const float*)d_in[4];
    const float* b0  = (const float*)d_in[5];
    const float* gm0 = (const float*)d_in[6];
    const float* be0 = (const float*)d_in[7];
    const float* W1  = (const float*)d_in[8];
    const float* as1 = (const float*)d_in[9];
    const float* ad1 = (const float*)d_in[10];
    const float* b1  = (const float*)d_in[11];
    const float* gm1 = (const float*)d_in[12];
    const float* be1 = (const float*)d_in[13];
    const float* Wc  = (const float*)d_in[14];
    const float* bc  = (const float*)d_in[15];
    float* out = (float*)d_out;

    float *h0, *hbn0, *h1, *hbn1;
    __nv_bfloat16 *xsp, *a1sp, *w0sp, *w1sp;
    cudaGetSymbolAddress((void**)&h0,   g_h0);
    cudaGetSymbolAddress((void**)&hbn0, g_hbn0);
    cudaGetSymbolAddress((void**)&h1,   g_h1);
    cudaGetSymbolAddress((void**)&hbn1, g_hbn1);
    cudaGetSymbolAddress((void**)&xsp,  g_xsp);
    cudaGetSymbolAddress((void**)&a1sp, g_a1sp);
    cudaGetSymbolAddress((void**)&w0sp, g_w0sp);
    cudaGetSymbolAddress((void**)&w1sp, g_w1sp);

    const int TB = 256;
    const int gEH   = (ET * H + TB - 1) / TB;
    const int gNH32 = (NN * H * 32 + TB - 1) / TB;
    const int gNF   = (NN * HID + TB - 1) / TB;
    const int MT    = (NN + 127) / 128;   // 79

    // ===== operand conversions =====
    split_a_kernel<<<(NN * 256 + TB - 1) / TB, TB>>>(x, xsp, NN);
    split_bT_kernel<<<(256 * 256 + TB - 1) / TB, TB>>>(W0, w0sp, 256);
    split_bT_kernel<<<(256 * 2048 + TB - 1) / TB, TB>>>(W1, w1sp, 2048);

    // ===== layer 0 =====
    {
        dim3 g(HID / 128, MT);
        mma_gemm_kernel<<<g, 256>>>(xsp, w0sp, h0, NN, HID);
    }
    scores_kernel<<<gNH32, TB>>>(h0, as0, ad0, 32);
    zero_seg_kernel<<<(NN * H + TB - 1) / TB, TB>>>();
    zero_acc_kernel<<<gNF, TB>>>();
    edge_p1_kernel<<<gEH, TB>>>(ei);
    edge_p2_kernel<<<gEH, TB>>>(ei);
    agg0_kernel<<<ET, TB>>>(ei, h0);
    zero_bn_kernel<<<1, HID>>>();
    bn_stats_kernel<<<(NN + 49) / 50, HID>>>(b0, 1.0f);
    bn_apply_kernel<<<gNF, TB>>>(b0, 1.0f, gm0, be0, nullptr, hbn0, a1sp);

    // ===== layer 1 =====
    {
        dim3 g((H * HID) / 128, MT);
        mma_gemm_kernel<<<g, 256>>>(a1sp, w1sp, h1, NN, H * HID);
    }
    scores_kernel<<<gNH32, TB>>>(h1, as1, ad1, 256);
    zero_seg_kernel<<<(NN * H + TB - 1) / TB, TB>>>();
    zero_acc_kernel<<<gNF, TB>>>();
    edge_p1_kernel<<<gEH, TB>>>(ei);
    edge_p2_kernel<<<gEH, TB>>>(ei);
    agg1_kernel<<<ET, TB>>>(ei, h1);
    zero_bn_kernel<<<1, HID>>>();
    bn_stats_kernel<<<(NN + 49) / 50, HID>>>(b1, 0.125f);
    bn_apply_kernel<<<gNF, TB>>>(b1, 0.125f, gm1, be1, hbn0, hbn1, nullptr);

    // ===== classifier =====
    {
        dim3 g((NC + 63) / 64, (NN + 63) / 64);
        gemm_kernel<<<g, TB>>>(hbn1, Wc, bc, out, NN, NC, 256);
    }
}

// round 10
// speedup vs baseline: 1.5194x; 1.2255x over previous
#include <cuda_runtime.h>
#include <cuda_bf16.h>
#include <math.h>
#include <stdint.h>

#define NN    10000
#define E0    160000
#define ET    (E0 + NN)
#define H     8
#define HID   256
#define NC    40
#define EPSV  1e-5f
#define KSP   768            // layer0 split-K: [hi | lo | hi] x [hi | hi | lo]
#define KOUT  6144           // layer1 output GEMM split-K (3 x 2048)

// ---------------- scratch ----------------
__device__ float    g_h0[(size_t)NN * HID];
__device__ float    g_hbn0[(size_t)NN * HID];
__device__ float    g_hbn1[(size_t)NN * HID];
__device__ float    g_acc[(size_t)NN * HID];
__device__ float    g_ssrc[NN * H];
__device__ float    g_sdst[NN * H];
__device__ unsigned g_m[NN * H];
__device__ float    g_den[NN * H];
__device__ float    g_esc[(size_t)ET * H];
__device__ float    g_bnsum[HID];
__device__ float    g_bnsq[HID];
__device__ float    g_wsrc[256 * H];                 // W1^T a_src1  [k][h]
__device__ float    g_wdst[256 * H];
// edge sort by dst
__device__ int      g_cnt[NN];
__device__ int      g_start[NN + 1];
__device__ int      g_cur[NN];
__device__ int      g_sorted[ET];
// bf16 split operands
__device__ __nv_bfloat16 g_xsp [(size_t)NN * KSP];   // x split [N, 768]
__device__ __nv_bfloat16 g_w0sp[(size_t)256 * KSP];  // W0^T split [No, 768]
__device__ __nv_bfloat16 g_a1sp[(size_t)NN * KOUT];  // per-head agg of hbn0, split [N, 6144]
__device__ __nv_bfloat16 g_w1sp[(size_t)256 * KOUT]; // reshaped W1, split [256, 6144]

// ---------------- helpers ----------------
__device__ __forceinline__ uint32_t smem_u32(const void* p) {
    uint32_t a;
    asm("{ .reg .u64 t; cvta.to.shared.u64 t, %1; cvt.u32.u64 %0, t; }" : "=r"(a) : "l"(p));
    return a;
}
__device__ __forceinline__ void cp16(uint32_t dst, const void* src, bool pred) {
    int sz = pred ? 16 : 0;
    asm volatile("cp.async.cg.shared.global [%0], [%1], 16, %2;"
                 :: "r"(dst), "l"(src), "r"(sz));
}
__device__ __forceinline__ void ldm_x4(uint32_t* r, uint32_t addr) {
    asm volatile("ldmatrix.sync.aligned.m8n8.x4.shared.b16 {%0,%1,%2,%3}, [%4];"
                 : "=r"(r[0]), "=r"(r[1]), "=r"(r[2]), "=r"(r[3]) : "r"(addr));
}
__device__ __forceinline__ void mma16816(float* c, const uint32_t* a, uint32_t b0, uint32_t b1) {
    asm volatile("mma.sync.aligned.m16n8k16.row.col.f32.bf16.bf16.f32 "
                 "{%0,%1,%2,%3}, {%4,%5,%6,%7}, {%8,%9}, {%0,%1,%2,%3};"
                 : "+f"(c[0]), "+f"(c[1]), "+f"(c[2]), "+f"(c[3])
                 : "r"(a[0]), "r"(a[1]), "r"(a[2]), "r"(a[3]), "r"(b0), "r"(b1));
}
__device__ __forceinline__ unsigned fflip(float f) {
    unsigned u = __float_as_uint(f);
    return u ^ ((u & 0x80000000u) ? 0xFFFFFFFFu : 0x80000000u);
}
__device__ __forceinline__ float funflip(unsigned u) {
    return __uint_as_float(u ^ ((u & 0x80000000u) ? 0x80000000u : 0xFFFFFFFFu));
}
__device__ __forceinline__ void edge_sd(const int* __restrict__ ei, int e, int& s, int& d) {
    if (e < E0) { s = ei[e]; d = ei[E0 + e]; }
    else        { s = e - E0; d = s; }
}
__device__ __forceinline__ int edge_src(const int* __restrict__ ei, int e) {
    return (e < E0) ? ei[e] : e - E0;
}

// ---------------- split conversion kernels ----------------
__global__ void split_a_kernel(const float* __restrict__ src, __nv_bfloat16* __restrict__ dst,
                               int rows) {
    int i = blockIdx.x * blockDim.x + threadIdx.x;
    if (i >= rows * 256) return;
    int r = i >> 8, k = i & 255;
    float v = src[i];
    __nv_bfloat16 h = __float2bfloat16(v);
    __nv_bfloat16 l = __float2bfloat16(v - __bfloat162float(h));
    __nv_bfloat16* p = dst + (size_t)r * KSP;
    p[k] = h; p[256 + k] = l; p[512 + k] = h;
}
// W0 [256][No] fp32 -> [No][768] bf16 [hi | hi | lo]
__global__ void split_bT_kernel(const float* __restrict__ W, __nv_bfloat16* __restrict__ dst,
                                int No) {
    int i = blockIdx.x * blockDim.x + threadIdx.x;
    if (i >= 256 * No) return;
    int k = i / No, n = i % No;
    float v = W[i];
    __nv_bfloat16 h = __float2bfloat16(v);
    __nv_bfloat16 l = __float2bfloat16(v - __bfloat162float(h));
    __nv_bfloat16* p = dst + (size_t)n * KSP;
    p[k] = h; p[256 + k] = h; p[512 + k] = l;
}
// W1 [256][2048] -> w1sp [c=0..255][j=h*256+k] = W1[k][h*256+c], split [hi|hi|lo] over K=6144
__global__ void split_b1_kernel(const float* __restrict__ W1) {
    int i = blockIdx.x * blockDim.x + threadIdx.x;
    if (i >= 256 * 2048) return;
    int c = i >> 11, j = i & 2047;
    int hh = j >> 8, k = j & 255;
    float v = W1[(size_t)k * 2048 + hh * 256 + c];
    __nv_bfloat16 h = __float2bfloat16(v);
    __nv_bfloat16 l = __float2bfloat16(v - __bfloat162float(h));
    __nv_bfloat16* p = g_w1sp + (size_t)c * KOUT;
    p[j] = h; p[2048 + j] = h; p[4096 + j] = l;
}
// wsrc[k][h] = sum_c W1[k, h*256+c] * a_src1[h,c]  (and wdst)
__global__ void watt_kernel(const float* __restrict__ W1, const float* __restrict__ as1,
                            const float* __restrict__ ad1) {
    int g = (blockIdx.x * blockDim.x + threadIdx.x) >> 5;
    int lane = threadIdx.x & 31;
    if (g >= 256 * H) return;
    int k = g >> 3, hh = g & 7;
    const float* wr = W1 + (size_t)k * 2048 + hh * 256;
    const float* a1 = as1 + hh * 256;
    const float* a2 = ad1 + hh * 256;
    float s1 = 0.f, s2 = 0.f;
    for (int j = lane; j < 256; j += 32) { float w = wr[j]; s1 += w * a1[j]; s2 += w * a2[j]; }
    #pragma unroll
    for (int o = 16; o; o >>= 1) {
        s1 += __shfl_down_sync(0xffffffffu, s1, o);
        s2 += __shfl_down_sync(0xffffffffu, s2, o);
    }
    if (lane == 0) { g_wsrc[k * 8 + hh] = s1; g_wdst[k * 8 + hh] = s2; }
}

// ---------------- edge counting sort by dst ----------------
__global__ void zero_cnt_kernel() {
    int i = blockIdx.x * blockDim.x + threadIdx.x;
    if (i < NN) g_cnt[i] = 0;
}
__global__ void hist_kernel(const int* __restrict__ ei) {
    int e = blockIdx.x * blockDim.x + threadIdx.x;
    if (e >= ET) return;
    int d = (e < E0) ? ei[E0 + e] : e - E0;
    atomicAdd(&g_cnt[d], 1);
}
__global__ void scan_kernel() {
    __shared__ int partial[1024];
    int t = threadIdx.x;
    int base = t * 10;
    int loc[10]; int s = 0;
    #pragma unroll
    for (int i = 0; i < 10; i++) {
        int idx = base + i;
        int c = (idx < NN) ? g_cnt[idx] : 0;
        loc[i] = c; s += c;
    }
    partial[t] = s;
    __syncthreads();
    if (t == 0) {
        int run = 0;
        for (int i = 0; i < 1024; i++) { int tmp = partial[i]; partial[i] = run; run += tmp; }
    }
    __syncthreads();
    int run = partial[t];
    #pragma unroll
    for (int i = 0; i < 10; i++) {
        int idx = base + i;
        if (idx < NN) { g_start[idx] = run; g_cur[idx] = run; run += loc[i]; }
    }
    if (t == 1023) g_start[NN] = run;
}
__global__ void scatter_kernel(const int* __restrict__ ei) {
    int e = blockIdx.x * blockDim.x + threadIdx.x;
    if (e >= ET) return;
    int d = (e < E0) ? ei[E0 + e] : e - E0;
    int pos = atomicAdd(&g_cur[d], 1);
    g_sorted[pos] = e;
}

// ---------------- bf16 mma.sync GEMM, 4-stage cp.async pipeline ----------------
// C[M,Nt] = A[M,Kd] @ Bt[Nt,Kd]^T, tile 128x128, BK=32, 8 warps (4Mx2N)
#define BK     32
#define SROWB  80                     // smem bytes per row (64B data + 16 pad)
#define STG_B  (128 * SROWB * 2)      // A+B per stage = 20480
#define GSMEM  (4 * STG_B)            // 81920
__global__ __launch_bounds__(256, 1)
void mma_gemm_kernel(const __nv_bfloat16* __restrict__ A, const __nv_bfloat16* __restrict__ Bt,
                     float* __restrict__ C, int M, int Nt, int Kd) {
    extern __shared__ char dsm[];
    const int KT = Kd / BK;
    const int tid  = threadIdx.x;
    const int lane = tid & 31, wid = tid >> 5;
    const int wm = (wid & 3) * 32;
    const int wn = (wid >> 2) * 64;
    const int m0 = blockIdx.y * 128;
    const int n0 = blockIdx.x * 128;
    const uint32_t sbase = smem_u32(dsm);

    int v0 = tid, v1 = tid + 256;
    int ar0 = v0 >> 2, ac0 = v0 & 3;
    int ar1 = v1 >> 2, ac1 = v1 & 3;
    bool p0 = (m0 + ar0) < M, p1 = (m0 + ar1) < M;
    int cm0 = p0 ? (m0 + ar0) : 0, cm1 = p1 ? (m0 + ar1) : 0;

    float c[2][8][4];
    #pragma unroll
    for (int i = 0; i < 2; i++)
        #pragma unroll
        for (int j = 0; j < 8; j++)
            #pragma unroll
            for (int q = 0; q < 4; q++) c[i][j][q] = 0.f;

    auto issue = [&](int kt) {
        uint32_t da = sbase + (uint32_t)(kt & 3) * STG_B;
        uint32_t db = da + 128 * SROWB;
        int k0 = kt * BK;
        cp16(da + (uint32_t)(ar0 * 80 + ac0 * 16), A + (size_t)cm0 * Kd + k0 + ac0 * 8, p0);
        cp16(da + (uint32_t)(ar1 * 80 + ac1 * 16), A + (size_t)cm1 * Kd + k0 + ac1 * 8, p1);
        cp16(db + (uint32_t)(ar0 * 80 + ac0 * 16), Bt + (size_t)(n0 + ar0) * Kd + k0 + ac0 * 8, true);
        cp16(db + (uint32_t)(ar1 * 80 + ac1 * 16), Bt + (size_t)(n0 + ar1) * Kd + k0 + ac1 * 8, true);
        asm volatile("cp.async.commit_group;");
    };

    issue(0); issue(1); issue(2);
    for (int kt = 0; kt < KT; kt++) {
        if (kt + 3 < KT) {
            issue(kt + 3);
            asm volatile("cp.async.wait_group 3;");
        } else {
            asm volatile("cp.async.wait_group 0;");
        }
        __syncthreads();

        uint32_t da = sbase + (uint32_t)(kt & 3) * STG_B;
        uint32_t db = da + 128 * SROWB;
        #pragma unroll
        for (int ks = 0; ks < 2; ks++) {
            uint32_t a[2][4], b[4][4];
            #pragma unroll
            for (int mi = 0; mi < 2; mi++) {
                uint32_t addr = da + (uint32_t)((wm + mi * 16 + (lane & 15)) * 80
                                              + (ks * 16 + (lane >> 4) * 8) * 2);
                ldm_x4(a[mi], addr);
            }
            #pragma unroll
            for (int ni = 0; ni < 4; ni++) {
                uint32_t addr = db + (uint32_t)((wn + ni * 16 + ((lane >> 4) << 3) + (lane & 7)) * 80
                                              + (ks * 16 + ((lane >> 3) & 1) * 8) * 2);
                ldm_x4(b[ni], addr);
            }
            #pragma unroll
            for (int mi = 0; mi < 2; mi++)
                #pragma unroll
                for (int nj = 0; nj < 8; nj++)
                    mma16816(c[mi][nj], a[mi], b[nj >> 1][(nj & 1) * 2 + 0],
                             b[nj >> 1][(nj & 1) * 2 + 1]);
        }
        __syncthreads();
    }

    #pragma unroll
    for (int mi = 0; mi < 2; mi++) {
        int gm = m0 + wm + mi * 16 + (lane >> 2);
        #pragma unroll
        for (int nj = 0; nj < 8; nj++) {
            int gn = n0 + wn + nj * 8 + (lane & 3) * 2;
            if (gm < M)
                *reinterpret_cast<float2*>(C + (size_t)gm * Nt + gn) =
                    make_float2(c[mi][nj][0], c[mi][nj][1]);
            if (gm + 8 < M)
                *reinterpret_cast<float2*>(C + (size_t)(gm + 8) * Nt + gn) =
                    make_float2(c[mi][nj][2], c[mi][nj][3]);
        }
    }
}

// ---------------- SIMT GEMM (classifier) ----------------
__global__ void gemm_kernel(const float* __restrict__ A, const float* __restrict__ B,
                            const float* __restrict__ bias, float* __restrict__ C,
                            int M, int N, int K) {
    __shared__ float As[16][64];
    __shared__ float Bs[16][64];
    const int tid = threadIdx.x;
    const int tx = tid & 15, ty = tid >> 4;
    const int row0 = blockIdx.y * 64;
    const int col0 = blockIdx.x * 64;
    float acc[4][4] = {};
    for (int k0 = 0; k0 < K; k0 += 16) {
        #pragma unroll
        for (int i = 0; i < 4; i++) {
            int m = (tid >> 4) + i * 16, kk = tid & 15, gm = row0 + m;
            As[kk][m] = (gm < M) ? A[(size_t)gm * K + k0 + kk] : 0.f;
        }
        #pragma unroll
        for (int i = 0; i < 4; i++) {
            int kk = (tid >> 6) + i * 4, nn = tid & 63, gn = col0 + nn;
            Bs[kk][nn] = (gn < N) ? B[(size_t)(k0 + kk) * N + gn] : 0.f;
        }
        __syncthreads();
        #pragma unroll
        for (int kk = 0; kk < 16; kk++) {
            float ra[4], rb[4];
            #pragma unroll
            for (int i = 0; i < 4; i++) ra[i] = As[kk][ty * 4 + i];
            #pragma unroll
            for (int j = 0; j < 4; j++) rb[j] = Bs[kk][tx * 4 + j];
            #pragma unroll
            for (int i = 0; i < 4; i++)
                #pragma unroll
                for (int j = 0; j < 4; j++)
                    acc[i][j] += ra[i] * rb[j];
        }
        __syncthreads();
    }
    #pragma unroll
    for (int i = 0; i < 4; i++) {
        int gm = row0 + ty * 4 + i;
        if (gm >= M) continue;
        #pragma unroll
        for (int j = 0; j < 4; j++) {
            int gn = col0 + tx * 4 + j;
            if (gn < N) C[(size_t)gm * N + gn] = acc[i][j] + (bias ? bias[gn] : 0.f);
        }
    }
}

// ---------------- attention scores ----------------
// layer0: per (node, head) dot with a_src0/a_dst0 on h0 [N, 8, 32]
__global__ void scores_kernel(const float* __restrict__ h, const float* __restrict__ asr,
                              const float* __restrict__ ads, int C) {
    int gw = (blockIdx.x * blockDim.x + threadIdx.x) >> 5;
    int lane = threadIdx.x & 31;
    if (gw >= NN * H) return;
    int n = gw / H, hh = gw % H;
    const float* hp = h + (size_t)n * H * C + (size_t)hh * C;
    const float* a1 = asr + hh * C;
    const float* a2 = ads + hh * C;
    float s1 = 0.f, s2 = 0.f;
    for (int c = lane; c < C; c += 32) {
        float v = hp[c];
        s1 += v * a1[c];
        s2 += v * a2[c];
    }
    #pragma unroll
    for (int o = 16; o; o >>= 1) {
        s1 += __shfl_down_sync(0xffffffffu, s1, o);
        s2 += __shfl_down_sync(0xffffffffu, s2, o);
    }
    if (lane == 0) { g_ssrc[gw] = s1; g_sdst[gw] = s2; }
}
// layer1: s[n,h] = hbn0[n,:] @ w{src,dst}[:,h], one warp per node
__global__ void score1_kernel(const float* __restrict__ hbn0) {
    __shared__ float sws[H * 256];   // [h][k]
    __shared__ float swd[H * 256];
    int tid = threadIdx.x;
    for (int i = tid; i < 2048; i += 256) {
        int k = i >> 3, hh = i & 7;          // g_wsrc is [k][h]
        sws[hh * 256 + k] = g_wsrc[i];
        swd[hh * 256 + k] = g_wdst[i];
    }
    __syncthreads();
    int w = tid >> 5, lane = tid & 31;
    int n = blockIdx.x * 8 + w;
    if (n >= NN) return;
    float v[8];
    #pragma unroll
    for (int j = 0; j < 8; j++) v[j] = hbn0[(size_t)n * 256 + j * 32 + lane];
    #pragma unroll
    for (int hh = 0; hh < H; hh++) {
        float s1 = 0.f, s2 = 0.f;
        #pragma unroll
        for (int j = 0; j < 8; j++) {
            int k = j * 32 + lane;
            s1 += v[j] * sws[hh * 256 + k];
            s2 += v[j] * swd[hh * 256 + k];
        }
        #pragma unroll
        for (int o = 16; o; o >>= 1) {
            s1 += __shfl_down_sync(0xffffffffu, s1, o);
            s2 += __shfl_down_sync(0xffffffffu, s2, o);
        }
        if (lane == 0) { g_ssrc[n * 8 + hh] = s1; g_sdst[n * 8 + hh] = s2; }
    }
}

// ---------------- zero/init ----------------
__global__ void zero_seg_kernel() {
    int i = blockIdx.x * blockDim.x + threadIdx.x;
    if (i < NN * H) { g_m[i] = 0u; g_den[i] = 0.f; }
}
__global__ void zero_bn_kernel() {
    int i = threadIdx.x;
    g_bnsum[i] = 0.f; g_bnsq[i] = 0.f;
}

// ---------------- edge softmax passes ----------------
__global__ void edge_p1_kernel(const int* __restrict__ ei) {
    int idx = blockIdx.x * blockDim.x + threadIdx.x;
    if (idx >= ET * H) return;
    int e = idx >> 3, hh = idx & 7;
    int s, d; edge_sd(ei, e, s, d);
    float sc = g_ssrc[s * H + hh] + g_sdst[d * H + hh];
    sc = sc > 0.f ? sc : 0.2f * sc;
    g_esc[idx] = sc;
    atomicMax(&g_m[d * H + hh], fflip(sc));
}
__global__ void edge_p2_kernel(const int* __restrict__ ei) {
    int idx = blockIdx.x * blockDim.x + threadIdx.x;
    if (idx >= ET * H) return;
    int e = idx >> 3, hh = idx & 7;
    int s, d; edge_sd(ei, e, s, d);
    float m = funflip(g_m[d * H + hh]);
    float ev = expf(g_esc[idx] - m);
    g_esc[idx] = ev;
    atomicAdd(&g_den[d * H + hh], ev);
}

// ---------------- atomic-free aggregation over dst-sorted edges ----------------
// layer 0: block per dst, thread owns output col (head = col>>5); writes g_acc row
__global__ void agg0_sorted_kernel(const int* __restrict__ ei, const float* __restrict__ h0) {
    int d = blockIdx.x;
    int tid = threadIdx.x, w = tid >> 5;
    int e0 = g_start[d], e1 = g_start[d + 1];
    float acc = 0.f;
    for (int i = e0; i < e1; i++) {
        int e = g_sorted[i];
        int s = edge_src(ei, e);
        acc += g_esc[e * 8 + w] * h0[(size_t)s * 256 + tid];
    }
    float rden = 1.f / g_den[d * 8 + w];
    g_acc[(size_t)d * 256 + tid] = acc * rden;
}
// layer 1: block per dst, thread owns k=tid; 8 head-accumulators; fused hi/lo split write
__global__ void agg1_sorted_kernel(const int* __restrict__ ei, const float* __restrict__ hbn0) {
    int d = blockIdx.x;
    int t = threadIdx.x;
    float acc[8] = {0.f, 0.f, 0.f, 0.f, 0.f, 0.f, 0.f, 0.f};
    int e0 = g_start[d], e1 = g_start[d + 1];
    for (int i = e0; i < e1; i++) {
        int e = g_sorted[i];
        int s = edge_src(ei, e);
        const float4* ep = reinterpret_cast<const float4*>(g_esc + (size_t)e * 8);
        float4 a0 = ep[0], a1 = ep[1];
        float v = hbn0[(size_t)s * 256 + t];
        acc[0] += a0.x * v; acc[1] += a0.y * v; acc[2] += a0.z * v; acc[3] += a0.w * v;
        acc[4] += a1.x * v; acc[5] += a1.y * v; acc[6] += a1.z * v; acc[7] += a1.w * v;
    }
    const float4* dp = reinterpret_cast<const float4*>(g_den + d * 8);
    float4 d0 = dp[0], d1 = dp[1];
    float rd[8] = {1.f / d0.x, 1.f / d0.y, 1.f / d0.z, 1.f / d0.w,
                   1.f / d1.x, 1.f / d1.y, 1.f / d1.z, 1.f / d1.w};
    __nv_bfloat16* p = g_a1sp + (size_t)d * KOUT;
    #pragma unroll
    for (int hh = 0; hh < 8; hh++) {
        float y = acc[hh] * rd[hh];
        __nv_bfloat16 h = __float2bfloat16(y);
        __nv_bfloat16 l = __float2bfloat16(y - __bfloat162float(h));
        int j = hh * 256 + t;
        p[j] = h; p[2048 + j] = l; p[4096 + j] = h;
    }
}

// ---------------- batch norm ----------------
__global__ void bn_stats_kernel(const float* __restrict__ bias, float scale) {
    int c = threadIdx.x;
    float b = bias[c];
    int r0 = blockIdx.x * 50;
    int r1 = r0 + 50; if (r1 > NN) r1 = NN;
    float s = 0.f, q = 0.f;
    for (int r = r0; r < r1; r++) {
        float v = g_acc[(size_t)r * HID + c] * scale + b;
        s += v; q += v * v;
    }
    atomicAdd(&g_bnsum[c], s);
    atomicAdd(&g_bnsq[c], q);
}
__global__ void bn_apply_kernel(const float* __restrict__ bias, float scale,
                                const float* __restrict__ gma, const float* __restrict__ bet,
                                const float* __restrict__ resid, float* __restrict__ out) {
    size_t i = (size_t)blockIdx.x * blockDim.x + threadIdx.x;
    if (i >= (size_t)NN * HID) return;
    int c = (int)(i & 255);
    float v = g_acc[i] * scale + bias[c];
    float mu = g_bnsum[c] * (1.0f / NN);
    float var = g_bnsq[c] * (1.0f / NN) - mu * mu;
    float y = gma[c] * (v - mu) * rsqrtf(var + EPSV) + bet[c];
    y = y > 0.f ? y : expm1f(y);
    if (resid) y += resid[i];
    out[i] = y;
}

// ---------------- launch ----------------
extern "C" void kernel_launch(void* const* d_in, const int* in_sizes, int n_in,
                              void* d_out, int out_size) {
    const float* x   = (const float*)d_in[0];
    const int*   ei  = (const int*)  d_in[1];
    const float* W0  = (const float*)d_in[2];
    const float* as0 = (const float*)d_in[3];
    const float* ad0 = (const float*)d_in[4];
    const float* b0  = (const float*)d_in[5];
    const float* gm0 = (const float*)d_in[6];
    const float* be0 = (const float*)d_in[7];
    const float* W1  = (const float*)d_in[8];
    const float* as1 = (const float*)d_in[9];
    const float* ad1 = (const float*)d_in[10];
    const float* b1  = (const float*)d_in[11];
    const float* gm1 = (const float*)d_in[12];
    const float* be1 = (const float*)d_in[13];
    const float* Wc  = (const float*)d_in[14];
    const float* bc  = (const float*)d_in[15];
    float* out = (float*)d_out;

    float *h0, *hbn0, *hbn1, *acc;
    __nv_bfloat16 *xsp, *a1sp, *w0sp, *w1sp;
    cudaGetSymbolAddress((void**)&h0,   g_h0);
    cudaGetSymbolAddress((void**)&hbn0, g_hbn0);
    cudaGetSymbolAddress((void**)&hbn1, g_hbn1);
    cudaGetSymbolAddress((void**)&acc,  g_acc);
    cudaGetSymbolAddress((void**)&xsp,  g_xsp);
    cudaGetSymbolAddress((void**)&a1sp, g_a1sp);
    cudaGetSymbolAddress((void**)&w0sp, g_w0sp);
    cudaGetSymbolAddress((void**)&w1sp, g_w1sp);

    static bool attr_done = false;
    if (!attr_done) {
        cudaFuncSetAttribute(mma_gemm_kernel,
                             cudaFuncAttributeMaxDynamicSharedMemorySize, GSMEM);
        attr_done = true;
    }

    const int TB = 256;
    const int gEH   = (ET * H + TB - 1) / TB;
    const int gNH32 = (NN * H * 32 + TB - 1) / TB;
    const int gNF   = (NN * HID + TB - 1) / TB;
    const int gET   = (ET + TB - 1) / TB;
    const int MT    = (NN + 127) / 128;   // 79

    // ===== operand prep =====
    split_a_kernel<<<(NN * 256 + TB - 1) / TB, TB>>>(x, xsp, NN);
    split_bT_kernel<<<(256 * 256 + TB - 1) / TB, TB>>>(W0, w0sp, 256);
    split_b1_kernel<<<(256 * 2048 + TB - 1) / TB, TB>>>(W1);
    watt_kernel<<<(256 * H * 32 + TB - 1) / TB, TB>>>(W1, as1, ad1);

    // ===== edge sort by dst =====
    zero_cnt_kernel<<<(NN + TB - 1) / TB, TB>>>();
    hist_kernel<<<gET, TB>>>(ei);
    scan_kernel<<<1, 1024>>>();
    scatter_kernel<<<gET, TB>>>(ei);

    // ===== layer 0 =====
    {
        dim3 g(HID / 128, MT);
        mma_gemm_kernel<<<g, 256, GSMEM>>>(xsp, w0sp, h0, NN, HID, KSP);
    }
    scores_kernel<<<gNH32, TB>>>(h0, as0, ad0, 32);
    zero_seg_kernel<<<(NN * H + TB - 1) / TB, TB>>>();
    edge_p1_kernel<<<gEH, TB>>>(ei);
    edge_p2_kernel<<<gEH, TB>>>(ei);
    agg0_sorted_kernel<<<NN, TB>>>(ei, h0);
    zero_bn_kernel<<<1, HID>>>();
    bn_stats_kernel<<<(NN + 49) / 50, HID>>>(b0, 1.0f);
    bn_apply_kernel<<<gNF, TB>>>(b0, 1.0f, gm0, be0, nullptr, hbn0);

    // ===== layer 1 (projection commuted past aggregation) =====
    score1_kernel<<<(NN + 7) / 8, TB>>>(hbn0);
    zero_seg_kernel<<<(NN * H + TB - 1) / TB, TB>>>();
    edge_p1_kernel<<<gEH, TB>>>(ei);
    edge_p2_kernel<<<gEH, TB>>>(ei);
    agg1_sorted_kernel<<<NN, TB>>>(ei, hbn0);
    {
        dim3 g(HID / 128, MT);
        mma_gemm_kernel<<<g, 256, GSMEM>>>(a1sp, w1sp, acc, NN, HID, KOUT);
    }
    zero_bn_kernel<<<1, HID>>>();
    bn_stats_kernel<<<(NN + 49) / 50, HID>>>(b1, 0.125f);
    bn_apply_kernel<<<gNF, TB>>>(b1, 0.125f, gm1, be1, hbn0, hbn1);

    // ===== classifier =====
    {
        dim3 g((NC + 63) / 64, (NN + 63) / 64);
        gemm_kernel<<<g, TB>>>(hbn1, Wc, bc, out, NN, NC, 256);
    }
}

// round 14
// speedup vs baseline: 1.6339x; 1.0754x over previous
#include <cuda_runtime.h>
#include <cuda_bf16.h>
#include <math.h>
#include <stdint.h>

#define NN    10000
#define E0    160000
#define ET    (E0 + NN)
#define H     8
#define HID   256
#define NC    40
#define EPSV  1e-5f
#define KSP   768            // layer0 split-K: [hi | lo | hi] x [hi | hi | lo]
#define KOUT  6144           // layer1 output GEMM split-K (3 x 2048)

// ---------------- scratch ----------------
__device__ float    g_h0[(size_t)NN * HID];
__device__ float    g_hbn0[(size_t)NN * HID];
__device__ float    g_hbn1[(size_t)NN * HID];
__device__ float    g_acc[(size_t)NN * HID];
__device__ float    g_ssrc[NN * H];
__device__ float    g_sdst[NN * H];
__device__ float    g_bnsum[HID];
__device__ float    g_bnsq[HID];
__device__ float    g_wsrc[256 * H];                 // W1^T a_src1  [k][h]
__device__ float    g_wdst[256 * H];
// edge sort by dst
__device__ int      g_cnt[NN];
__device__ int      g_start[NN + 1];
__device__ int      g_cur[NN];
__device__ int      g_sorted[ET];
// bf16 split operands
__device__ __nv_bfloat16 g_xsp [(size_t)NN * KSP];
__device__ __nv_bfloat16 g_w0sp[(size_t)256 * KSP];
__device__ __nv_bfloat16 g_a1sp[(size_t)NN * KOUT];
__device__ __nv_bfloat16 g_w1sp[(size_t)256 * KOUT];

// ---------------- helpers ----------------
__device__ __forceinline__ uint32_t smem_u32(const void* p) {
    uint32_t a;
    asm("{ .reg .u64 t; cvta.to.shared.u64 t, %1; cvt.u32.u64 %0, t; }" : "=r"(a) : "l"(p));
    return a;
}
__device__ __forceinline__ void cp16(uint32_t dst, const void* src, bool pred) {
    int sz = pred ? 16 : 0;
    asm volatile("cp.async.cg.shared.global [%0], [%1], 16, %2;"
                 :: "r"(dst), "l"(src), "r"(sz));
}
__device__ __forceinline__ void ldm_x4(uint32_t* r, uint32_t addr) {
    asm volatile("ldmatrix.sync.aligned.m8n8.x4.shared.b16 {%0,%1,%2,%3}, [%4];"
                 : "=r"(r[0]), "=r"(r[1]), "=r"(r[2]), "=r"(r[3]) : "r"(addr));
}
__device__ __forceinline__ void mma16816(float* c, const uint32_t* a, uint32_t b0, uint32_t b1) {
    asm volatile("mma.sync.aligned.m16n8k16.row.col.f32.bf16.bf16.f32 "
                 "{%0,%1,%2,%3}, {%4,%5,%6,%7}, {%8,%9}, {%0,%1,%2,%3};"
                 : "+f"(c[0]), "+f"(c[1]), "+f"(c[2]), "+f"(c[3])
                 : "r"(a[0]), "r"(a[1]), "r"(a[2]), "r"(a[3]), "r"(b0), "r"(b1));
}
__device__ __forceinline__ unsigned fflip(float f) {
    unsigned u = __float_as_uint(f);
    return u ^ ((u & 0x80000000u) ? 0xFFFFFFFFu : 0x80000000u);
}
__device__ __forceinline__ float funflip(unsigned u) {
    return __uint_as_float(u ^ ((u & 0x80000000u) ? 0x80000000u : 0xFFFFFFFFu));
}
__device__ __forceinline__ int edge_src(const int* __restrict__ ei, int e) {
    return (e < E0) ? ei[e] : e - E0;
}

// ---------------- split conversion kernels ----------------
__global__ void split_a_kernel(const float* __restrict__ src, __nv_bfloat16* __restrict__ dst,
                               int rows) {
    int i = blockIdx.x * blockDim.x + threadIdx.x;
    if (i >= rows * 256) return;
    int r = i >> 8, k = i & 255;
    float v = src[i];
    __nv_bfloat16 h = __float2bfloat16(v);
    __nv_bfloat16 l = __float2bfloat16(v - __bfloat162float(h));
    __nv_bfloat16* p = dst + (size_t)r * KSP;
    p[k] = h; p[256 + k] = l; p[512 + k] = h;
}
__global__ void split_bT_kernel(const float* __restrict__ W, __nv_bfloat16* __restrict__ dst,
                                int No) {
    int i = blockIdx.x * blockDim.x + threadIdx.x;
    if (i >= 256 * No) return;
    int k = i / No, n = i % No;
    float v = W[i];
    __nv_bfloat16 h = __float2bfloat16(v);
    __nv_bfloat16 l = __float2bfloat16(v - __bfloat162float(h));
    __nv_bfloat16* p = dst + (size_t)n * KSP;
    p[k] = h; p[256 + k] = h; p[512 + k] = l;
}
__global__ void split_b1_kernel(const float* __restrict__ W1) {
    int i = blockIdx.x * blockDim.x + threadIdx.x;
    if (i >= 256 * 2048) return;
    int c = i >> 11, j = i & 2047;
    int hh = j >> 8, k = j & 255;
    float v = W1[(size_t)k * 2048 + hh * 256 + c];
    __nv_bfloat16 h = __float2bfloat16(v);
    __nv_bfloat16 l = __float2bfloat16(v - __bfloat162float(h));
    __nv_bfloat16* p = g_w1sp + (size_t)c * KOUT;
    p[j] = h; p[2048 + j] = h; p[4096 + j] = l;
}
__global__ void watt_kernel(const float* __restrict__ W1, const float* __restrict__ as1,
                            const float* __restrict__ ad1) {
    int g = (blockIdx.x * blockDim.x + threadIdx.x) >> 5;
    int lane = threadIdx.x & 31;
    if (g >= 256 * H) return;
    int k = g >> 3, hh = g & 7;
    const float* wr = W1 + (size_t)k * 2048 + hh * 256;
    const float* a1 = as1 + hh * 256;
    const float* a2 = ad1 + hh * 256;
    float s1 = 0.f, s2 = 0.f;
    for (int j = lane; j < 256; j += 32) { float w = wr[j]; s1 += w * a1[j]; s2 += w * a2[j]; }
    #pragma unroll
    for (int o = 16; o; o >>= 1) {
        s1 += __shfl_down_sync(0xffffffffu, s1, o);
        s2 += __shfl_down_sync(0xffffffffu, s2, o);
    }
    if (lane == 0) { g_wsrc[k * 8 + hh] = s1; g_wdst[k * 8 + hh] = s2; }
}

// ---------------- edge counting sort by dst ----------------
__global__ void zero_cnt_kernel() {
    int i = blockIdx.x * blockDim.x + threadIdx.x;
    if (i < NN) g_cnt[i] = 0;
}
__global__ void hist_kernel(const int* __restrict__ ei) {
    int e = blockIdx.x * blockDim.x + threadIdx.x;
    if (e >= ET) return;
    int d = (e < E0) ? ei[E0 + e] : e - E0;
    atomicAdd(&g_cnt[d], 1);
}
__global__ void scan_kernel() {
    __shared__ int partial[1024];
    int t = threadIdx.x;
    int base = t * 10;
    int loc[10]; int s = 0;
    #pragma unroll
    for (int i = 0; i < 10; i++) {
        int idx = base + i;
        int c = (idx < NN) ? g_cnt[idx] : 0;
        loc[i] = c; s += c;
    }
    partial[t] = s;
    __syncthreads();
    if (t == 0) {
        int run = 0;
        for (int i = 0; i < 1024; i++) { int tmp = partial[i]; partial[i] = run; run += tmp; }
    }
    __syncthreads();
    int run = partial[t];
    #pragma unroll
    for (int i = 0; i < 10; i++) {
        int idx = base + i;
        if (idx < NN) { g_start[idx] = run; g_cur[idx] = run; run += loc[i]; }
    }
    if (t == 1023) g_start[NN] = run;
}
__global__ void scatter_kernel(const int* __restrict__ ei) {
    int e = blockIdx.x * blockDim.x + threadIdx.x;
    if (e >= ET) return;
    int d = (e < E0) ? ei[E0 + e] : e - E0;
    int pos = atomicAdd(&g_cur[d], 1);
    g_sorted[pos] = e;
}

// ---------------- bf16 mma.sync GEMM, 4-stage cp.async pipeline ----------------
#define BK     32
#define SROWB  80
#define STG_B  (128 * SROWB * 2)
#define GSMEM  (4 * STG_B)
__global__ __launch_bounds__(256, 1)
void mma_gemm_kernel(const __nv_bfloat16* __restrict__ A, const __nv_bfloat16* __restrict__ Bt,
                     float* __restrict__ C, int M, int Nt, int Kd) {
    extern __shared__ char dsm[];
    const int KT = Kd / BK;
    const int tid  = threadIdx.x;
    const int lane = tid & 31, wid = tid >> 5;
    const int wm = (wid & 3) * 32;
    const int wn = (wid >> 2) * 64;
    const int m0 = blockIdx.y * 128;
    const int n0 = blockIdx.x * 128;
    const uint32_t sbase = smem_u32(dsm);

    int v0 = tid, v1 = tid + 256;
    int ar0 = v0 >> 2, ac0 = v0 & 3;
    int ar1 = v1 >> 2, ac1 = v1 & 3;
    bool p0 = (m0 + ar0) < M, p1 = (m0 + ar1) < M;
    int cm0 = p0 ? (m0 + ar0) : 0, cm1 = p1 ? (m0 + ar1) : 0;

    float c[2][8][4];
    #pragma unroll
    for (int i = 0; i < 2; i++)
        #pragma unroll
        for (int j = 0; j < 8; j++)
            #pragma unroll
            for (int q = 0; q < 4; q++) c[i][j][q] = 0.f;

    auto issue = [&](int kt) {
        uint32_t da = sbase + (uint32_t)(kt & 3) * STG_B;
        uint32_t db = da + 128 * SROWB;
        int k0 = kt * BK;
        cp16(da + (uint32_t)(ar0 * 80 + ac0 * 16), A + (size_t)cm0 * Kd + k0 + ac0 * 8, p0);
        cp16(da + (uint32_t)(ar1 * 80 + ac1 * 16), A + (size_t)cm1 * Kd + k0 + ac1 * 8, p1);
        cp16(db + (uint32_t)(ar0 * 80 + ac0 * 16), Bt + (size_t)(n0 + ar0) * Kd + k0 + ac0 * 8, true);
        cp16(db + (uint32_t)(ar1 * 80 + ac1 * 16), Bt + (size_t)(n0 + ar1) * Kd + k0 + ac1 * 8, true);
        asm volatile("cp.async.commit_group;");
    };

    issue(0); issue(1); issue(2);
    for (int kt = 0; kt < KT; kt++) {
        if (kt + 3 < KT) {
            issue(kt + 3);
            asm volatile("cp.async.wait_group 3;");
        } else {
            asm volatile("cp.async.wait_group 0;");
        }
        __syncthreads();

        uint32_t da = sbase + (uint32_t)(kt & 3) * STG_B;
        uint32_t db = da + 128 * SROWB;
        #pragma unroll
        for (int ks = 0; ks < 2; ks++) {
            uint32_t a[2][4], b[4][4];
            #pragma unroll
            for (int mi = 0; mi < 2; mi++) {
                uint32_t addr = da + (uint32_t)((wm + mi * 16 + (lane & 15)) * 80
                                              + (ks * 16 + (lane >> 4) * 8) * 2);
                ldm_x4(a[mi], addr);
            }
            #pragma unroll
            for (int ni = 0; ni < 4; ni++) {
                uint32_t addr = db + (uint32_t)((wn + ni * 16 + ((lane >> 4) << 3) + (lane & 7)) * 80
                                              + (ks * 16 + ((lane >> 3) & 1) * 8) * 2);
                ldm_x4(b[ni], addr);
            }
            #pragma unroll
            for (int mi = 0; mi < 2; mi++)
                #pragma unroll
                for (int nj = 0; nj < 8; nj++)
                    mma16816(c[mi][nj], a[mi], b[nj >> 1][(nj & 1) * 2 + 0],
                             b[nj >> 1][(nj & 1) * 2 + 1]);
        }
        __syncthreads();
    }

    #pragma unroll
    for (int mi = 0; mi < 2; mi++) {
        int gm = m0 + wm + mi * 16 + (lane >> 2);
        #pragma unroll
        for (int nj = 0; nj < 8; nj++) {
            int gn = n0 + wn + nj * 8 + (lane & 3) * 2;
            if (gm < M)
                *reinterpret_cast<float2*>(C + (size_t)gm * Nt + gn) =
                    make_float2(c[mi][nj][0], c[mi][nj][1]);
            if (gm + 8 < M)
                *reinterpret_cast<float2*>(C + (size_t)(gm + 8) * Nt + gn) =
                    make_float2(c[mi][nj][2], c[mi][nj][3]);
        }
    }
}

// ---------------- SIMT GEMM (classifier) ----------------
__global__ void gemm_kernel(const float* __restrict__ A, const float* __restrict__ B,
                            const float* __restrict__ bias, float* __restrict__ C,
                            int M, int N, int K) {
    __shared__ float As[16][64];
    __shared__ float Bs[16][64];
    const int tid = threadIdx.x;
    const int tx = tid & 15, ty = tid >> 4;
    const int row0 = blockIdx.y * 64;
    const int col0 = blockIdx.x * 64;
    float acc[4][4] = {};
    for (int k0 = 0; k0 < K; k0 += 16) {
        #pragma unroll
        for (int i = 0; i < 4; i++) {
            int m = (tid >> 4) + i * 16, kk = tid & 15, gm = row0 + m;
            As[kk][m] = (gm < M) ? A[(size_t)gm * K + k0 + kk] : 0.f;
        }
        #pragma unroll
        for (int i = 0; i < 4; i++) {
            int kk = (tid >> 6) + i * 4, nn = tid & 63, gn = col0 + nn;
            Bs[kk][nn] = (gn < N) ? B[(size_t)(k0 + kk) * N + gn] : 0.f;
        }
        __syncthreads();
        #pragma unroll
        for (int kk = 0; kk < 16; kk++) {
            float ra[4], rb[4];
            #pragma unroll
            for (int i = 0; i < 4; i++) ra[i] = As[kk][ty * 4 + i];
            #pragma unroll
            for (int j = 0; j < 4; j++) rb[j] = Bs[kk][tx * 4 + j];
            #pragma unroll
            for (int i = 0; i < 4; i++)
                #pragma unroll
                for (int j = 0; j < 4; j++)
                    acc[i][j] += ra[i] * rb[j];
        }
        __syncthreads();
    }
    #pragma unroll
    for (int i = 0; i < 4; i++) {
        int gm = row0 + ty * 4 + i;
        if (gm >= M) continue;
        #pragma unroll
        for (int j = 0; j < 4; j++) {
            int gn = col0 + tx * 4 + j;
            if (gn < N) C[(size_t)gm * N + gn] = acc[i][j] + (bias ? bias[gn] : 0.f);
        }
    }
}

// ---------------- attention scores ----------------
__global__ void scores_kernel(const float* __restrict__ h, const float* __restrict__ asr,
                              const float* __restrict__ ads, int C) {
    int gw = (blockIdx.x * blockDim.x + threadIdx.x) >> 5;
    int lane = threadIdx.x & 31;
    if (gw >= NN * H) return;
    int n = gw / H, hh = gw % H;
    const float* hp = h + (size_t)n * H * C + (size_t)hh * C;
    const float* a1 = asr + hh * C;
    const float* a2 = ads + hh * C;
    float s1 = 0.f, s2 = 0.f;
    for (int c = lane; c < C; c += 32) {
        float v = hp[c];
        s1 += v * a1[c];
        s2 += v * a2[c];
    }
    #pragma unroll
    for (int o = 16; o; o >>= 1) {
        s1 += __shfl_down_sync(0xffffffffu, s1, o);
        s2 += __shfl_down_sync(0xffffffffu, s2, o);
    }
    if (lane == 0) { g_ssrc[gw] = s1; g_sdst[gw] = s2; }
}
__global__ void score1_kernel(const float* __restrict__ hbn0) {
    __shared__ float sws[H * 256];
    __shared__ float swd[H * 256];
    int tid = threadIdx.x;
    for (int i = tid; i < 2048; i += 256) {
        int k = i >> 3, hh = i & 7;
        sws[hh * 256 + k] = g_wsrc[i];
        swd[hh * 256 + k] = g_wdst[i];
    }
    __syncthreads();
    int w = tid >> 5, lane = tid & 31;
    int n = blockIdx.x * 8 + w;
    if (n >= NN) return;
    float v[8];
    #pragma unroll
    for (int j = 0; j < 8; j++) v[j] = hbn0[(size_t)n * 256 + j * 32 + lane];
    #pragma unroll
    for (int hh = 0; hh < H; hh++) {
        float s1 = 0.f, s2 = 0.f;
        #pragma unroll
        for (int j = 0; j < 8; j++) {
            int k = j * 32 + lane;
            s1 += v[j] * sws[hh * 256 + k];
            s2 += v[j] * swd[hh * 256 + k];
        }
        #pragma unroll
        for (int o = 16; o; o >>= 1) {
            s1 += __shfl_down_sync(0xffffffffu, s1, o);
            s2 += __shfl_down_sync(0xffffffffu, s2, o);
        }
        if (lane == 0) { g_ssrc[n * 8 + hh] = s1; g_sdst[n * 8 + hh] = s2; }
    }
}

// ---------------- fused softmax + aggregation (block per dst, sorted edges) ----------------
// Phase A: per-head segment max + denom in shm (scores recomputed from g_ssrc/g_sdst).
// Phase B: 32-edge chunks; 256 threads = 32x8 alphas in one step; aggregate rows.
#define CH 32
struct SmaxSh {
    unsigned m[H];
    float den[H], rd[H], sdst[H], mf[H];
    int   srcs[CH];
    float al[CH][H];
};
template <int LAYER>
__global__ void fused_agg_kernel(const int* __restrict__ ei, const float* __restrict__ feat) {
    __shared__ SmaxSh sh;
    const int d = blockIdx.x, t = threadIdx.x;
    const int e0 = g_start[d];
    const int cnt = g_start[d + 1] - e0;

    if (t < H) { sh.m[t] = 0u; sh.den[t] = 0.f; sh.sdst[t] = g_sdst[d * H + t]; }
    __syncthreads();

    // max
    for (int idx = t; idx < cnt * H; idx += 256) {
        int el = idx >> 3, hh = idx & 7;
        int s = edge_src(ei, g_sorted[e0 + el]);
        float sc = g_ssrc[s * H + hh] + sh.sdst[hh];
        sc = sc > 0.f ? sc : 0.2f * sc;
        atomicMax(&sh.m[hh], fflip(sc));
    }
    __syncthreads();
    if (t < H) sh.mf[t] = funflip(sh.m[t]);
    __syncthreads();
    // denom
    for (int idx = t; idx < cnt * H; idx += 256) {
        int el = idx >> 3, hh = idx & 7;
        int s = edge_src(ei, g_sorted[e0 + el]);
        float sc = g_ssrc[s * H + hh] + sh.sdst[hh];
        sc = sc > 0.f ? sc : 0.2f * sc;
        atomicAdd(&sh.den[hh], expf(sc - sh.mf[hh]));
    }
    __syncthreads();
    if (t < H) sh.rd[t] = 1.f / sh.den[t];
    __syncthreads();

    float acc0 = 0.f;
    float acc1[H] = {0.f, 0.f, 0.f, 0.f, 0.f, 0.f, 0.f, 0.f};

    for (int c0 = 0; c0 < cnt; c0 += CH) {
        int ce = min(CH, cnt - c0);
        if (t < ce * H) {
            int el = t >> 3, hh = t & 7;
            int s = edge_src(ei, g_sorted[e0 + c0 + el]);
            float sc = g_ssrc[s * H + hh] + sh.sdst[hh];
            sc = sc > 0.f ? sc : 0.2f * sc;
            sh.al[el][hh] = expf(sc - sh.mf[hh]) * sh.rd[hh];
            if (hh == 0) sh.srcs[el] = s;
        }
        __syncthreads();
        for (int j = 0; j < ce; j++) {
            float v = feat[(size_t)sh.srcs[j] * 256 + t];
            if (LAYER == 0) {
                acc0 += sh.al[j][t >> 5] * v;
            } else {
                #pragma unroll
                for (int hh = 0; hh < H; hh++) acc1[hh] += sh.al[j][hh] * v;
            }
        }
        __syncthreads();
    }

    if (LAYER == 0) {
        g_acc[(size_t)d * 256 + t] = acc0;
    } else {
        __nv_bfloat16* p = g_a1sp + (size_t)d * KOUT;
        #pragma unroll
        for (int hh = 0; hh < H; hh++) {
            float y = acc1[hh];
            __nv_bfloat16 h = __float2bfloat16(y);
            __nv_bfloat16 l = __float2bfloat16(y - __bfloat162float(h));
            int j = hh * 256 + t;
            p[j] = h; p[2048 + j] = l; p[4096 + j] = h;
        }
    }
}

// ---------------- batch norm ----------------
__global__ void zero_bn_kernel() {
    int i = threadIdx.x;
    g_bnsum[i] = 0.f; g_bnsq[i] = 0.f;
}
__global__ void bn_stats_kernel(const float* __restrict__ bias, float scale) {
    int c = threadIdx.x;
    float b = bias[c];
    int r0 = blockIdx.x * 50;
    int r1 = r0 + 50; if (r1 > NN) r1 = NN;
    float s = 0.f, q = 0.f;
    for (int r = r0; r < r1; r++) {
        float v = g_acc[(size_t)r * HID + c] * scale + b;
        s += v; q += v * v;
    }
    atomicAdd(&g_bnsum[c], s);
    atomicAdd(&g_bnsq[c], q);
}
__global__ void bn_apply_kernel(const float* __restrict__ bias, float scale,
                                const float* __restrict__ gma, const float* __restrict__ bet,
                                const float* __restrict__ resid, float* __restrict__ out) {
    size_t i = (size_t)blockIdx.x * blockDim.x + threadIdx.x;
    if (i >= (size_t)NN * HID) return;
    int c = (int)(i & 255);
    float v = g_acc[i] * scale + bias[c];
    float mu = g_bnsum[c] * (1.0f / NN);
    float var = g_bnsq[c] * (1.0f / NN) - mu * mu;
    float y = gma[c] * (v - mu) * rsqrtf(var + EPSV) + bet[c];
    y = y > 0.f ? y : expm1f(y);
    if (resid) y += resid[i];
    out[i] = y;
}

// ---------------- launch ----------------
extern "C" void kernel_launch(void* const* d_in, const int* in_sizes, int n_in,
                              void* d_out, int out_size) {
    const float* x   = (const float*)d_in[0];
    const int*   ei  = (const int*)  d_in[1];
    const float* W0  = (const float*)d_in[2];
    const float* as0 = (const float*)d_in[3];
    const float* ad0 = (const float*)d_in[4];
    const float* b0  = (const float*)d_in[5];
    const float* gm0 = (const float*)d_in[6];
    const float* be0 = (const float*)d_in[7];
    const float* W1  = (const float*)d_in[8];
    const float* as1 = (const float*)d_in[9];
    const float* ad1 = (const float*)d_in[10];
    const float* b1  = (const float*)d_in[11];
    const float* gm1 = (const float*)d_in[12];
    const float* be1 = (const float*)d_in[13];
    const float* Wc  = (const float*)d_in[14];
    const float* bc  = (const float*)d_in[15];
    float* out = (float*)d_out;

    float *h0, *hbn0, *hbn1, *acc;
    __nv_bfloat16 *xsp, *a1sp, *w0sp, *w1sp;
    cudaGetSymbolAddress((void**)&h0,   g_h0);
    cudaGetSymbolAddress((void**)&hbn0, g_hbn0);
    cudaGetSymbolAddress((void**)&hbn1, g_hbn1);
    cudaGetSymbolAddress((void**)&acc,  g_acc);
    cudaGetSymbolAddress((void**)&xsp,  g_xsp);
    cudaGetSymbolAddress((void**)&a1sp, g_a1sp);
    cudaGetSymbolAddress((void**)&w0sp, g_w0sp);
    cudaGetSymbolAddress((void**)&w1sp, g_w1sp);

    cudaFuncSetAttribute(mma_gemm_kernel,
                         cudaFuncAttributeMaxDynamicSharedMemorySize, GSMEM);

    const int TB = 256;
    const int gNH32 = (NN * H * 32 + TB - 1) / TB;
    const int gNF   = (NN * HID + TB - 1) / TB;
    const int gET   = (ET + TB - 1) / TB;
    const int MT    = (NN + 127) / 128;

    // ===== operand prep =====
    split_a_kernel<<<(NN * 256 + TB - 1) / TB, TB>>>(x, xsp, NN);
    split_bT_kernel<<<(256 * 256 + TB - 1) / TB, TB>>>(W0, w0sp, 256);
    split_b1_kernel<<<(256 * 2048 + TB - 1) / TB, TB>>>(W1);
    watt_kernel<<<(256 * H * 32 + TB - 1) / TB, TB>>>(W1, as1, ad1);

    // ===== edge sort by dst =====
    zero_cnt_kernel<<<(NN + TB - 1) / TB, TB>>>();
    hist_kernel<<<gET, TB>>>(ei);
    scan_kernel<<<1, 1024>>>();
    scatter_kernel<<<gET, TB>>>(ei);

    // ===== layer 0 =====
    {
        dim3 g(HID / 128, MT);
        mma_gemm_kernel<<<g, 256, GSMEM>>>(xsp, w0sp, h0, NN, HID, KSP);
    }
    scores_kernel<<<gNH32, TB>>>(h0, as0, ad0, 32);
    fused_agg_kernel<0><<<NN, TB>>>(ei, h0);
    zero_bn_kernel<<<1, HID>>>();
    bn_stats_kernel<<<(NN + 49) / 50, HID>>>(b0, 1.0f);
    bn_apply_kernel<<<gNF, TB>>>(b0, 1.0f, gm0, be0, nullptr, hbn0);

    // ===== layer 1 (projection commuted past aggregation) =====
    score1_kernel<<<(NN + 7) / 8, TB>>>(hbn0);
    fused_agg_kernel<1><<<NN, TB>>>(ei, hbn0);
    {
        dim3 g(HID / 128, MT);
        mma_gemm_kernel<<<g, 256, GSMEM>>>(a1sp, w1sp, acc, NN, HID, KOUT);
    }
    zero_bn_kernel<<<1, HID>>>();
    bn_stats_kernel<<<(NN + 49) / 50, HID>>>(b1, 0.125f);
    bn_apply_kernel<<<gNF, TB>>>(b1, 0.125f, gm1, be1, hbn0, hbn1);

    // ===== classifier =====
    {
        dim3 g((NC + 63) / 64, (NN + 63) / 64);
        gemm_kernel<<<g, TB>>>(hbn1, Wc, bc, out, NN, NC, 256);
    }
}